// round 2
// baseline (speedup 1.0000x reference)
#include <cuda_runtime.h>
#include <cstdint>

#define N_NODES 8192
#define N_EDGES 24576
#define D_FEAT  64
#define N_QUBITS 16
#define PI_F 3.14159265358979f

// Scratch (no device mallocs allowed)
__device__ int      g_idx_o[N_EDGES];
__device__ int      g_idx_i[N_EDGES];
__device__ unsigned g_min_bits;
__device__ unsigned g_max_bits;
__device__ unsigned g_arrive;

// Coalesced float4 streaming scan of both one-hot incidence matrices.
// M is [N_NODES, N_EDGES] row-major; nonzero at linear pos p means
// idx[p % N_EDGES] = p / N_EDGES. Also resets the global scalars used by
// the fused mlp+norm kernel (safe: nothing else reads them in this kernel).
__global__ void scan_kernel(const float4* __restrict__ Mo,
                            const float4* __restrict__ Mi,
                            long total4) {
    if (blockIdx.x == 0 && threadIdx.x == 0) {
        g_min_bits = 0x7F800000u;  // +inf
        g_max_bits = 0x00000000u;  // 0.0f (relu outputs are >= 0)
        g_arrive   = 0u;
    }
    long start  = (long)blockIdx.x * blockDim.x + threadIdx.x;
    long stride = (long)gridDim.x * blockDim.x;

    for (long i = start; i < total4; i += stride) {
        float4 v = Mo[i];
        if (v.x != 0.f || v.y != 0.f || v.z != 0.f || v.w != 0.f) {
            long base = i * 4;
            int n = (int)(base / N_EDGES);
            int e = (int)(base % N_EDGES);
            if (v.x != 0.f) g_idx_o[e + 0] = n;
            if (v.y != 0.f) g_idx_o[e + 1] = n;
            if (v.z != 0.f) g_idx_o[e + 2] = n;
            if (v.w != 0.f) g_idx_o[e + 3] = n;
        }
    }
    for (long i = start; i < total4; i += stride) {
        float4 v = Mi[i];
        if (v.x != 0.f || v.y != 0.f || v.z != 0.f || v.w != 0.f) {
            long base = i * 4;
            int n = (int)(base / N_EDGES);
            int e = (int)(base % N_EDGES);
            if (v.x != 0.f) g_idx_i[e + 0] = n;
            if (v.y != 0.f) g_idx_i[e + 1] = n;
            if (v.z != 0.f) g_idx_i[e + 2] = n;
            if (v.w != 0.f) g_idx_i[e + 3] = n;
        }
    }
}

// Fused MLP + global min/max + normalize. 4 lanes per edge.
// Lane j of an edge handles 32 contiguous dims of the concatenated
// B = [X[src], X[tgt]] (j=0,1 -> source halves; j=2,3 -> target halves),
// accumulates 16 partial dot products, butterfly-reduces across the 4 lanes,
// then writes qubits [4j, 4j+4) after a single-wave grid barrier resolves
// the global min/max.
__global__ void __launch_bounds__(256, 3)
edge_mlp_kernel(const float* __restrict__ X,
                const float* __restrict__ W,   // [128,16] row-major
                const float* __restrict__ b,   // [16]
                float* __restrict__ out) {
    __shared__ float4 sW4[2 * D_FEAT * N_QUBITS / 4];   // 8 KB (512 float4)
    __shared__ float  sb[N_QUBITS];
    __shared__ float  s_min[8], s_max[8];
    __shared__ float  s_lo, s_hi;

    const int tid = threadIdx.x;
    const int j   = tid & 3;          // lane within edge group
    const int e   = blockIdx.x * 64 + (tid >> 2);

    // stage W into shared (512 float4, 256 threads -> 2 each)
    const float4* W4 = (const float4*)W;
    sW4[tid]       = W4[tid];
    sW4[tid + 256] = W4[tid + 256];
    if (tid < N_QUBITS) sb[tid] = b[tid];
    __syncthreads();

    // this lane's 32-float segment of B
    int node = (j < 2) ? g_idx_o[e] : g_idx_i[e];
    const float4* xsrc = (const float4*)(X + (long)node * D_FEAT) + (j & 1) * 8;
    const int base_row = j * 32;      // row offset into W

    float acc[N_QUBITS];
#pragma unroll
    for (int q = 0; q < N_QUBITS; q++) acc[q] = 0.0f;

#pragma unroll
    for (int d4 = 0; d4 < 8; d4++) {
        float4 v = xsrc[d4];
        const float4* wr = &sW4[(base_row + d4 * 4) * 4];
        float xs[4] = {v.x, v.y, v.z, v.w};
#pragma unroll
        for (int k = 0; k < 4; k++) {
            float4 w0 = wr[k * 4 + 0];
            float4 w1 = wr[k * 4 + 1];
            float4 w2 = wr[k * 4 + 2];
            float4 w3 = wr[k * 4 + 3];
            float xv = xs[k];
            acc[0]  = fmaf(xv, w0.x, acc[0]);
            acc[1]  = fmaf(xv, w0.y, acc[1]);
            acc[2]  = fmaf(xv, w0.z, acc[2]);
            acc[3]  = fmaf(xv, w0.w, acc[3]);
            acc[4]  = fmaf(xv, w1.x, acc[4]);
            acc[5]  = fmaf(xv, w1.y, acc[5]);
            acc[6]  = fmaf(xv, w1.z, acc[6]);
            acc[7]  = fmaf(xv, w1.w, acc[7]);
            acc[8]  = fmaf(xv, w2.x, acc[8]);
            acc[9]  = fmaf(xv, w2.y, acc[9]);
            acc[10] = fmaf(xv, w2.z, acc[10]);
            acc[11] = fmaf(xv, w2.w, acc[11]);
            acc[12] = fmaf(xv, w3.x, acc[12]);
            acc[13] = fmaf(xv, w3.y, acc[13]);
            acc[14] = fmaf(xv, w3.z, acc[14]);
            acc[15] = fmaf(xv, w3.w, acc[15]);
        }
    }

    // reduce across the 4 lanes of this edge (xor 1, xor 2 stay in group)
#pragma unroll
    for (int q = 0; q < N_QUBITS; q++) {
        acc[q] += __shfl_xor_sync(0xFFFFFFFF, acc[q], 1);
        acc[q] += __shfl_xor_sync(0xFFFFFFFF, acc[q], 2);
    }

    // this lane keeps its 4 qubits: h = relu(sum + bias)
    float h0 = fmaxf(acc[j * 4 + 0] + sb[j * 4 + 0], 0.0f);
    float h1 = fmaxf(acc[j * 4 + 1] + sb[j * 4 + 1], 0.0f);
    float h2 = fmaxf(acc[j * 4 + 2] + sb[j * 4 + 2], 0.0f);
    float h3 = fmaxf(acc[j * 4 + 3] + sb[j * 4 + 3], 0.0f);

    float tmin = fminf(fminf(h0, h1), fminf(h2, h3));
    float tmax = fmaxf(fmaxf(h0, h1), fmaxf(h2, h3));
#pragma unroll
    for (int off = 16; off > 0; off >>= 1) {
        tmin = fminf(tmin, __shfl_xor_sync(0xFFFFFFFF, tmin, off));
        tmax = fmaxf(tmax, __shfl_xor_sync(0xFFFFFFFF, tmax, off));
    }
    int wid = tid >> 5, lid = tid & 31;
    if (lid == 0) { s_min[wid] = tmin; s_max[wid] = tmax; }
    __syncthreads();

    if (tid == 0) {
        float bmin = s_min[0], bmax = s_max[0];
#pragma unroll
        for (int w = 1; w < 8; w++) {
            bmin = fminf(bmin, s_min[w]);
            bmax = fmaxf(bmax, s_max[w]);
        }
        // nonneg floats: uint bit pattern preserves ordering
        atomicMin(&g_min_bits, __float_as_uint(bmin));
        atomicMax(&g_max_bits, __float_as_uint(bmax));
        __threadfence();
        atomicAdd(&g_arrive, 1u);
        // single-wave grid barrier (grid=384 <= 148*3 resident slots)
        while (*((volatile unsigned*)&g_arrive) < gridDim.x) __nanosleep(64);
        s_lo = __uint_as_float(atomicAdd(&g_min_bits, 0u));
        s_hi = __uint_as_float(atomicAdd(&g_max_bits, 0u));
    }
    __syncthreads();

    float lo = s_lo;
    float s  = PI_F / (s_hi - lo);

    // coalesced: consecutive tid -> consecutive float4 of out [E,16]
    float4* o4 = (float4*)out;
    o4[(long)e * 4 + j] = make_float4((h0 - lo) * s, (h1 - lo) * s,
                                      (h2 - lo) * s, (h3 - lo) * s);
}

extern "C" void kernel_launch(void* const* d_in, const int* in_sizes, int n_in,
                              void* d_out, int out_size) {
    const float* X    = (const float*)d_in[0];   // [8192, 64]
    const float* Ri   = (const float*)d_in[1];   // [8192, 24576]
    const float* Ro   = (const float*)d_in[2];   // [8192, 24576]
    const float* W_in = (const float*)d_in[3];   // [128, 16]
    const float* b_in = (const float*)d_in[4];   // [16]
    float* out = (float*)d_out;                  // [24576, 16]

    const long total4 = (long)N_NODES * N_EDGES / 4;   // 50,331,648 float4s
    scan_kernel<<<148 * 16, 256>>>((const float4*)Ro, (const float4*)Ri, total4);

    edge_mlp_kernel<<<N_EDGES * 4 / 256, 256>>>(X, W_in, b_in, out);
}

// round 3
// speedup vs baseline: 1.0777x; 1.0777x over previous
#include <cuda_runtime.h>
#include <cstdint>

#define N_NODES 8192
#define N_EDGES 24576
#define D_FEAT  64
#define N_QUBITS 16
#define PI_F 3.14159265358979f

// Scratch (no device mallocs allowed)
__device__ int      g_idx_o[N_EDGES];
__device__ int      g_idx_i[N_EDGES];
__device__ float    g_H[N_NODES * 32];   // [n][0:16]=X[n]@W_top, [n][16:32]=X[n]@W_bot
__device__ unsigned g_min_bits;
__device__ unsigned g_max_bits;
__device__ unsigned g_arrive;

// ---------------------------------------------------------------------------
// Per-node precompute: Hs[n][q] = sum_d X[n][d] * W[d][q]
//                      Ht[n][q] = sum_d X[n][d] * W[64+d][q]
// One warp per node; lanes 0..15 -> Hs qubits, lanes 16..31 -> Ht qubits.
// Also resets the scalars used by the edge kernel (runs first each replay).
// ---------------------------------------------------------------------------
__global__ void __launch_bounds__(256)
node_kernel(const float* __restrict__ X,
            const float* __restrict__ W) {     // [128,16] row-major
    __shared__ float sW[2 * D_FEAT * N_QUBITS];   // 8 KB
    __shared__ float sX[8][D_FEAT];

    const int tid  = threadIdx.x;
    const int wid  = tid >> 5;
    const int lane = tid & 31;

    if (blockIdx.x == 0 && tid == 0) {
        g_min_bits = 0x7F800000u;   // +inf
        g_max_bits = 0x00000000u;   // relu outputs >= 0
        g_arrive   = 0u;
    }

    // stage W (512 float4 / 256 threads = 2 each)
    const float4* W4 = (const float4*)W;
    ((float4*)sW)[tid]       = W4[tid];
    ((float4*)sW)[tid + 256] = W4[tid + 256];

    const int n = blockIdx.x * 8 + wid;
    // each lane loads 2 contiguous floats of X[n]
    ((float2*)sX[wid])[lane] = ((const float2*)(X + (long)n * D_FEAT))[lane];
    __syncthreads();

    const int q    = lane & 15;
    const int half = lane >> 4;               // 0 = source weights, 1 = target
    const float* w = sW + half * D_FEAT * N_QUBITS + q;
    const float* x = sX[wid];

    float acc = 0.0f;
#pragma unroll
    for (int d = 0; d < D_FEAT; d++)
        acc = fmaf(x[d], w[d * N_QUBITS], acc);

    g_H[(long)n * 32 + lane] = acc;           // coalesced 128B per warp
}

// ---------------------------------------------------------------------------
// Coalesced float4 streaming scan of both one-hot incidence matrices.
// Nonzero at linear pos p of [N_NODES, N_EDGES] => idx[p % E] = p / E.
// ---------------------------------------------------------------------------
__global__ void scan_kernel(const float4* __restrict__ Mo,
                            const float4* __restrict__ Mi,
                            long total4) {
    long start  = (long)blockIdx.x * blockDim.x + threadIdx.x;
    long stride = (long)gridDim.x * blockDim.x;

    for (long i = start; i < total4; i += stride) {
        float4 v = Mo[i];
        if (v.x != 0.f || v.y != 0.f || v.z != 0.f || v.w != 0.f) {
            long base = i * 4;
            int n = (int)(base / N_EDGES);
            int e = (int)(base % N_EDGES);
            if (v.x != 0.f) g_idx_o[e + 0] = n;
            if (v.y != 0.f) g_idx_o[e + 1] = n;
            if (v.z != 0.f) g_idx_o[e + 2] = n;
            if (v.w != 0.f) g_idx_o[e + 3] = n;
        }
    }
    for (long i = start; i < total4; i += stride) {
        float4 v = Mi[i];
        if (v.x != 0.f || v.y != 0.f || v.z != 0.f || v.w != 0.f) {
            long base = i * 4;
            int n = (int)(base / N_EDGES);
            int e = (int)(base % N_EDGES);
            if (v.x != 0.f) g_idx_i[e + 0] = n;
            if (v.y != 0.f) g_idx_i[e + 1] = n;
            if (v.z != 0.f) g_idx_i[e + 2] = n;
            if (v.w != 0.f) g_idx_i[e + 3] = n;
        }
    }
}

// ---------------------------------------------------------------------------
// Edge stage: h[e] = relu(Hs[src[e]] + Ht[tgt[e]] + b); global min/max via
// atomics + single-wave grid barrier (96 blocks); normalize in-register;
// single coalesced store. One thread per edge.
// ---------------------------------------------------------------------------
__global__ void __launch_bounds__(256, 3)
edge_kernel(const float* __restrict__ b,
            float* __restrict__ out) {
    __shared__ float s_min[8], s_max[8];
    __shared__ float s_lo, s_hi;

    const int tid = threadIdx.x;
    const int e   = blockIdx.x * 256 + tid;

    const int src = g_idx_o[e];
    const int tgt = g_idx_i[e];

    const float4* hs = (const float4*)(g_H + (long)src * 32);
    const float4* ht = (const float4*)(g_H + (long)tgt * 32 + 16);
    const float4* b4 = (const float4*)b;

    float4 h[4];
    float tmin = 3.4e38f, tmax = 0.0f;
#pragma unroll
    for (int k = 0; k < 4; k++) {
        float4 a = hs[k];
        float4 c = ht[k];
        float4 bb = b4[k];
        h[k].x = fmaxf(a.x + c.x + bb.x, 0.0f);
        h[k].y = fmaxf(a.y + c.y + bb.y, 0.0f);
        h[k].z = fmaxf(a.z + c.z + bb.z, 0.0f);
        h[k].w = fmaxf(a.w + c.w + bb.w, 0.0f);
        tmin = fminf(tmin, fminf(fminf(h[k].x, h[k].y), fminf(h[k].z, h[k].w)));
        tmax = fmaxf(tmax, fmaxf(fmaxf(h[k].x, h[k].y), fmaxf(h[k].z, h[k].w)));
    }

#pragma unroll
    for (int off = 16; off > 0; off >>= 1) {
        tmin = fminf(tmin, __shfl_xor_sync(0xFFFFFFFF, tmin, off));
        tmax = fmaxf(tmax, __shfl_xor_sync(0xFFFFFFFF, tmax, off));
    }
    int wid = tid >> 5, lid = tid & 31;
    if (lid == 0) { s_min[wid] = tmin; s_max[wid] = tmax; }
    __syncthreads();

    if (tid == 0) {
        float bmin = s_min[0], bmax = s_max[0];
#pragma unroll
        for (int w = 1; w < 8; w++) {
            bmin = fminf(bmin, s_min[w]);
            bmax = fmaxf(bmax, s_max[w]);
        }
        // nonneg floats: uint bit pattern preserves ordering
        atomicMin(&g_min_bits, __float_as_uint(bmin));
        atomicMax(&g_max_bits, __float_as_uint(bmax));
        __threadfence();
        atomicAdd(&g_arrive, 1u);
        // single-wave grid barrier (96 blocks << 148*3 resident slots)
        while (*((volatile unsigned*)&g_arrive) < gridDim.x) __nanosleep(64);
        s_lo = __uint_as_float(atomicAdd(&g_min_bits, 0u));
        s_hi = __uint_as_float(atomicAdd(&g_max_bits, 0u));
    }
    __syncthreads();

    const float lo = s_lo;
    const float s  = PI_F / (s_hi - lo);

    float4* o4 = (float4*)(out + (long)e * N_QUBITS);
#pragma unroll
    for (int k = 0; k < 4; k++) {
        o4[k] = make_float4((h[k].x - lo) * s, (h[k].y - lo) * s,
                            (h[k].z - lo) * s, (h[k].w - lo) * s);
    }
}

extern "C" void kernel_launch(void* const* d_in, const int* in_sizes, int n_in,
                              void* d_out, int out_size) {
    const float* X    = (const float*)d_in[0];   // [8192, 64]
    const float* Ri   = (const float*)d_in[1];   // [8192, 24576]
    const float* Ro   = (const float*)d_in[2];   // [8192, 24576]
    const float* W_in = (const float*)d_in[3];   // [128, 16]
    const float* b_in = (const float*)d_in[4];   // [16]
    float* out = (float*)d_out;                  // [24576, 16]

    node_kernel<<<N_NODES / 8, 256>>>(X, W_in);

    const long total4 = (long)N_NODES * N_EDGES / 4;   // 50,331,648 float4s
    scan_kernel<<<148 * 16, 256>>>((const float4*)Ro, (const float4*)Ri, total4);

    edge_kernel<<<N_EDGES / 256, 256>>>(b_in, out);
}

// round 4
// speedup vs baseline: 1.0796x; 1.0018x over previous
#include <cuda_runtime.h>
#include <cstdint>

#define N_NODES 8192
#define N_EDGES 24576
#define D_FEAT  64
#define N_QUBITS 16
#define PI_F 3.14159265358979f

// Scratch (no device mallocs allowed)
__device__ int      g_idx_o[N_EDGES];
__device__ int      g_idx_i[N_EDGES];
__device__ float    g_H[N_NODES * 32];   // [n][0:16]=X[n]@W_top, [n][16:32]=X[n]@W_bot
__device__ unsigned g_min_bits;
__device__ unsigned g_max_bits;
__device__ unsigned g_arrive;

#define SCAN_BLOCKS (148 * 16)
#define SCAN_THREADS 256
#define NODE_BLOCKS (N_NODES / 8)        // 1024 blocks do node prologue

// ---------------------------------------------------------------------------
// Fused: (a) node precompute prologue on blocks < NODE_BLOCKS,
//        (b) streaming scan of both one-hot incidence matrices (interleaved,
//            unrolled x2 -> 4 independent LDG.128 in flight per iteration).
// Nonzero (==1.0f, bits 0x3F800000) at linear pos p of [N_NODES, N_EDGES]
// row-major means idx[p % E] = p / E. Integer OR test: nonzero bits <=> 1.0f.
// ---------------------------------------------------------------------------
__global__ void __launch_bounds__(SCAN_THREADS)
scan_kernel(const uint4* __restrict__ Mo,
            const uint4* __restrict__ Mi,
            const float* __restrict__ X,
            const float* __restrict__ W) {
    const int tid = threadIdx.x;

    if (blockIdx.x == 0 && tid == 0) {
        g_min_bits = 0x7F800000u;   // +inf
        g_max_bits = 0x00000000u;   // relu outputs >= 0
        g_arrive   = 0u;
    }

    // ---- node prologue: Hs[n][q], Ht[n][q] for 8 nodes per block ----
    if (blockIdx.x < NODE_BLOCKS) {
        __shared__ float sW[2 * D_FEAT * N_QUBITS];   // 8 KB
        __shared__ float sX[8][D_FEAT];

        const int wid  = tid >> 5;
        const int lane = tid & 31;

        const float4* W4 = (const float4*)W;
        ((float4*)sW)[tid]       = W4[tid];
        ((float4*)sW)[tid + 256] = W4[tid + 256];

        const int n = blockIdx.x * 8 + wid;
        ((float2*)sX[wid])[lane] = ((const float2*)(X + (long)n * D_FEAT))[lane];
        __syncthreads();

        const int q    = lane & 15;
        const int half = lane >> 4;   // 0 = W[0:64], 1 = W[64:128]
        const float* w = sW + half * D_FEAT * N_QUBITS + q;
        const float* x = sX[wid];

        float acc = 0.0f;
#pragma unroll
        for (int d = 0; d < D_FEAT; d++)
            acc = fmaf(x[d], w[d * N_QUBITS], acc);

        g_H[(long)n * 32 + lane] = acc;   // coalesced 128B per warp
    }

    // ---- streaming scan ----
    const long total4 = (long)N_NODES * N_EDGES / 4;
    const long stride = (long)SCAN_BLOCKS * SCAN_THREADS;
    long i = (long)blockIdx.x * SCAN_THREADS + tid;

#define PROCESS(v, I, IDX)                                              \
    if (((v).x | (v).y | (v).z | (v).w) != 0u) {                        \
        long base = (I) * 4;                                            \
        int n = (int)(base / N_EDGES);                                  \
        int e = (int)(base % N_EDGES);                                  \
        if ((v).x != 0u) IDX[e + 0] = n;                                \
        if ((v).y != 0u) IDX[e + 1] = n;                                \
        if ((v).z != 0u) IDX[e + 2] = n;                                \
        if ((v).w != 0u) IDX[e + 3] = n;                                \
    }

    for (; i + stride < total4; i += 2 * stride) {
        uint4 a0 = Mo[i];
        uint4 a1 = Mo[i + stride];
        uint4 b0 = Mi[i];
        uint4 b1 = Mi[i + stride];
        PROCESS(a0, i,          g_idx_o)
        PROCESS(a1, i + stride, g_idx_o)
        PROCESS(b0, i,          g_idx_i)
        PROCESS(b1, i + stride, g_idx_i)
    }
    for (; i < total4; i += stride) {
        uint4 a = Mo[i];
        uint4 b = Mi[i];
        PROCESS(a, i, g_idx_o)
        PROCESS(b, i, g_idx_i)
    }
#undef PROCESS
}

// ---------------------------------------------------------------------------
// Edge stage: h[e] = relu(Hs[src[e]] + Ht[tgt[e]] + b); global min/max via
// atomics + single-wave grid barrier (96 blocks); normalize in-register;
// single coalesced store. One thread per edge.
// ---------------------------------------------------------------------------
__global__ void __launch_bounds__(256, 3)
edge_kernel(const float* __restrict__ b,
            float* __restrict__ out) {
    __shared__ float s_min[8], s_max[8];
    __shared__ float s_lo, s_hi;

    const int tid = threadIdx.x;
    const int e   = blockIdx.x * 256 + tid;

    const int src = g_idx_o[e];
    const int tgt = g_idx_i[e];

    const float4* hs = (const float4*)(g_H + (long)src * 32);
    const float4* ht = (const float4*)(g_H + (long)tgt * 32 + 16);
    const float4* b4 = (const float4*)b;

    float4 h[4];
    float tmin = 3.4e38f, tmax = 0.0f;
#pragma unroll
    for (int k = 0; k < 4; k++) {
        float4 a = hs[k];
        float4 c = ht[k];
        float4 bb = b4[k];
        h[k].x = fmaxf(a.x + c.x + bb.x, 0.0f);
        h[k].y = fmaxf(a.y + c.y + bb.y, 0.0f);
        h[k].z = fmaxf(a.z + c.z + bb.z, 0.0f);
        h[k].w = fmaxf(a.w + c.w + bb.w, 0.0f);
        tmin = fminf(tmin, fminf(fminf(h[k].x, h[k].y), fminf(h[k].z, h[k].w)));
        tmax = fmaxf(tmax, fmaxf(fmaxf(h[k].x, h[k].y), fmaxf(h[k].z, h[k].w)));
    }

#pragma unroll
    for (int off = 16; off > 0; off >>= 1) {
        tmin = fminf(tmin, __shfl_xor_sync(0xFFFFFFFF, tmin, off));
        tmax = fmaxf(tmax, __shfl_xor_sync(0xFFFFFFFF, tmax, off));
    }
    int wid = tid >> 5, lid = tid & 31;
    if (lid == 0) { s_min[wid] = tmin; s_max[wid] = tmax; }
    __syncthreads();

    if (tid == 0) {
        float bmin = s_min[0], bmax = s_max[0];
#pragma unroll
        for (int w = 1; w < 8; w++) {
            bmin = fminf(bmin, s_min[w]);
            bmax = fmaxf(bmax, s_max[w]);
        }
        // nonneg floats: uint bit pattern preserves ordering
        atomicMin(&g_min_bits, __float_as_uint(bmin));
        atomicMax(&g_max_bits, __float_as_uint(bmax));
        __threadfence();
        atomicAdd(&g_arrive, 1u);
        // single-wave grid barrier (96 blocks << 148*3 resident slots)
        while (*((volatile unsigned*)&g_arrive) < gridDim.x) __nanosleep(64);
        s_lo = __uint_as_float(atomicAdd(&g_min_bits, 0u));
        s_hi = __uint_as_float(atomicAdd(&g_max_bits, 0u));
    }
    __syncthreads();

    const float lo = s_lo;
    const float s  = PI_F / (s_hi - lo);

    float4* o4 = (float4*)(out + (long)e * N_QUBITS);
#pragma unroll
    for (int k = 0; k < 4; k++) {
        o4[k] = make_float4((h[k].x - lo) * s, (h[k].y - lo) * s,
                            (h[k].z - lo) * s, (h[k].w - lo) * s);
    }
}

extern "C" void kernel_launch(void* const* d_in, const int* in_sizes, int n_in,
                              void* d_out, int out_size) {
    const float* X    = (const float*)d_in[0];   // [8192, 64]
    const float* Ri   = (const float*)d_in[1];   // [8192, 24576]
    const float* Ro   = (const float*)d_in[2];   // [8192, 24576]
    const float* W_in = (const float*)d_in[3];   // [128, 16]
    const float* b_in = (const float*)d_in[4];   // [16]
    float* out = (float*)d_out;                  // [24576, 16]

    scan_kernel<<<SCAN_BLOCKS, SCAN_THREADS>>>((const uint4*)Ro, (const uint4*)Ri,
                                               X, W_in);

    edge_kernel<<<N_EDGES / 256, 256>>>(b_in, out);
}